// round 14
// baseline (speedup 1.0000x reference)
#include <cuda_runtime.h>
#include <math.h>
#include <stdint.h>

#define FULLMASK 0xffffffffu

// pooled outputs (inputs to next layer)
__device__ __align__(16) float g_y1[64 * 320 * 768];
__device__ __align__(16) float g_y2[64 * 224 * 512];
__device__ __align__(16) float g_y3[64 * 144 * 256];
__device__ __align__(16) float g_y4[64 * 88 * 4];
// pre-pool conv outputs
__device__ __align__(16) float g_p1[64 * 320 * 1030];
__device__ __align__(16) float g_p2[64 * 224 * 772];
__device__ __align__(16) float g_p3[64 * 144 * 516];
__device__ __align__(16) float g_p4[64 * 88 * 258];

__device__ __forceinline__ unsigned long long fma2(unsigned long long a,
                                                   unsigned long long b,
                                                   unsigned long long c) {
    unsigned long long d;
    asm("fma.rn.f32x2 %0,%1,%2,%3;" : "=l"(d) : "l"(a), "l"(b), "l"(c));
    return d;
}
__device__ __forceinline__ void up2(unsigned long long v, float& x, float& y) {
    asm("mov.b64 {%0,%1},%2;" : "=f"(x), "=f"(y) : "l"(v));
}
__device__ __forceinline__ unsigned fkey(float f) {
    unsigned u = __float_as_uint(f);
    return (u & 0x80000000u) ? ~u : (u | 0x80000000u);
}
__device__ __forceinline__ float unfkey(unsigned k) {
    unsigned u = (k & 0x80000000u) ? (k ^ 0x80000000u) : ~k;
    return __uint_as_float(u);
}
// match-aggregated histogram add: one ATOMS per distinct bin per 32-batch
__device__ __forceinline__ void hist_add(unsigned* hist, unsigned bin, bool valid,
                                         int lane) {
    unsigned key = valid ? bin : 0xFFFFFFFFu;
    unsigned peers = __match_any_sync(FULLMASK, key);
    int leader = __ffs(peers) - 1;
    if (valid && lane == leader) atomicAdd(&hist[bin], (unsigned)__popc(peers));
}

#define CTH 128   // conv block
#define TS  128   // seq outputs per conv CTA
#define TT  8     // outputs per thread

__host__ __device__ constexpr int conv_smem_words(int IC, int NF, int KS) {
    const int SMT = TS + 2 * KS;
    return 2 * IC * SMT + 2 * (NF / 2) * IC * KS + 2 * (NF / 2);
}

// grouped conv (+fold) -> pre-pool gmem. grid.x = NG*NTILE, grid.y = B.
template <int IC, int NF, int KS, int SIN, bool GATHER>
__global__ void __launch_bounds__(CTH)
conv_kernel(const float* __restrict__ xin, const int* __restrict__ tokens,
            const float* __restrict__ emb, const float* __restrict__ w,
            const float* __restrict__ bias, float* __restrict__ pre) {
    constexpr int PAD = KS - 1, SOUT = SIN + KS - 1;
    constexpr int SMT = TS + 2 * KS;
    constexpr int NPAIR = NF / 2;
    constexpr int NTILE = (SOUT + TS - 1) / TS;
    constexpr int IPG = IC / 2;

    extern __shared__ float sm[];
    float* sm_in = sm;                          // IC*SMT dup pairs (v,v)
    float* sm_w  = sm_in + 2 * IC * SMT;        // NPAIR*IC*KS f32x2
    float* sm_b2 = sm_w + 2 * NPAIR * IC * KS;  // NPAIR f32x2

    const int j = blockIdx.x / NTILE;
    const int st = blockIdx.x % NTILE;
    const int b = blockIdx.y, tid = threadIdx.x;
    const int NG = gridDim.x / NTILE;
    const int CHT = NG * NF;
    const int obase = st * TS;

    if constexpr (GATHER) {
        for (int p = tid; p < SMT; p += CTH) {
            int i = obase + p - PAD;
            float2 e = make_float2(0.f, 0.f);
            if (i >= 0 && i < SIN) {
                int tok = tokens[b * SIN + i];
                e = ((const float2*)emb)[tok * 32 + j];
            }
            ((float2*)sm_in)[p]       = make_float2(e.x, e.x);
            ((float2*)sm_in)[SMT + p] = make_float2(e.y, e.y);
        }
    } else {
        const float* src = xin + ((size_t)b * (NG * IC) + (size_t)j * IC) * SIN;
        for (int idx = tid; idx < IC * SMT; idx += CTH) {
            int ic = idx / SMT, p = idx % SMT;
            int i = obase + p - PAD;
            float v = (i >= 0 && i < SIN) ? src[(size_t)ic * SIN + i] : 0.f;
            ((float2*)sm_in)[idx] = make_float2(v, v);
        }
    }
    for (int i = tid; i < NPAIR * IC * KS; i += CTH) {
        int fp = i % NPAIR, rest = i / NPAIR;
        int k = rest % KS, ic = rest / KS;
        int g = 2 * j + (ic >= IPG ? 1 : 0);
        int ich = ic % IPG;
        const float* wb = w + (size_t)(g * NF) * IPG * KS + ich * KS + k;
        sm_w[2 * i]     = wb[(size_t)(2 * fp) * (IPG * KS)];
        sm_w[2 * i + 1] = wb[(size_t)(2 * fp + 1) * (IPG * KS)];
    }
    for (int i = tid; i < NPAIR; i += CTH) {
        sm_b2[2 * i]     = bias[2 * j * NF + 2 * i]     + bias[(2 * j + 1) * NF + 2 * i];
        sm_b2[2 * i + 1] = bias[2 * j * NF + 2 * i + 1] + bias[(2 * j + 1) * NF + 2 * i + 1];
    }
    __syncthreads();

    constexpr int ITEMS = NPAIR * (TS / TT);
    for (int t = tid; t < ITEMS; t += CTH) {
        const int fp = t % NPAIR, ot = t / NPAIR, o0 = ot * TT;
        unsigned long long acc[TT];
        unsigned long long b2 = *(const unsigned long long*)(sm_b2 + 2 * fp);
#pragma unroll
        for (int tt = 0; tt < TT; tt++) acc[tt] = b2;
        const unsigned long long* xrow = (const unsigned long long*)sm_in + o0;
        const unsigned long long* wrow = (const unsigned long long*)sm_w + fp;
        for (int ic = 0; ic < IC; ic++) {
            unsigned long long wd[TT + KS - 1];
#pragma unroll
            for (int q = 0; q < TT + KS - 1; q++) wd[q] = xrow[ic * SMT + q];
#pragma unroll
            for (int k = 0; k < KS; k++) {
                unsigned long long wk = wrow[(ic * KS + k) * NPAIR];
#pragma unroll
                for (int tt = 0; tt < TT; tt++) acc[tt] = fma2(wd[k + tt], wk, acc[tt]);
            }
        }
        const int c0 = j * NF + 2 * fp;
        float* d0 = pre + ((size_t)b * CHT + c0) * SOUT;
        float* d1 = d0 + SOUT;
#pragma unroll
        for (int tt = 0; tt < TT; tt++) {
            int o = obase + o0 + tt;
            if (o < SOUT) {
                float x_, y_;
                up2(acc[tt], x_, y_);
                d0[o] = x_;
                d1[o] = y_;
            }
        }
    }
}

// pivot over 256-bin per-warp hist (8 bins/lane). updates r (r -= count above bin).
__device__ __forceinline__ int pivot256(const unsigned* hist, unsigned& r, int lane) {
    unsigned h[8], s = 0;
#pragma unroll
    for (int m = 0; m < 8; m++) { h[m] = hist[lane * 8 + m]; s += h[m]; }
    unsigned run = s;  // suffix sum over lanes (bins ascend with lane)
#pragma unroll
    for (int d = 1; d < 32; d <<= 1) {
        unsigned v = __shfl_down_sync(FULLMASK, run, d);
        if (lane + d < 32) run += v;
    }
    unsigned above = run - s;
    bool mine = (above < r) && (run >= r);
    unsigned a2 = above, gtc = 0;
    int bsel = 0;
    bool found = false;
#pragma unroll
    for (int m = 7; m >= 0; m--) {
        unsigned na = a2 + h[m];
        if (!found && na >= r) { found = true; bsel = lane * 8 + m; gtc = a2; }
        a2 = na;
    }
    unsigned msk = __ballot_sync(FULLMASK, mine);
    int src = __ffs(msk) - 1;
    bsel = __shfl_sync(FULLMASK, bsel, src);
    gtc  = __shfl_sync(FULLMASK, gtc, src);
    r -= gtc;
    return bsel;
}

// warp-per-row top-KOUT (order preserving, lax.top_k ties) + tanh.
// pass A caches keys in SMEM + match-aggregated hist; refines on LDS only.
template <int SOUT, int KOUT>
__global__ void __launch_bounds__(128)
kmax_kernel(const float* __restrict__ pre, float* __restrict__ yout) {
    constexpr int NP = SOUT / 2;  // SOUT even
    extern __shared__ unsigned ksm[];
    const int warp = threadIdx.x >> 5, lane = threadIdx.x & 31;
    const unsigned lmlt = (1u << lane) - 1u;
    unsigned* keys = ksm + warp * (SOUT + 256);
    unsigned* hist = keys + SOUT;

    const int row = blockIdx.x * 4 + warp;
    const float2* vals2 = (const float2*)(pre + (size_t)row * SOUT);
    float* dst = yout + (size_t)row * KOUT;

    unsigned r = KOUT;
#pragma unroll
    for (int m = 0; m < 8; m++) hist[lane * 8 + m] = 0;
    __syncwarp();
    // pass A: global read once, keys -> SMEM (ordered), top-byte hist (match-agg)
    for (int base = 0; base < NP; base += 32) {
        int i = base + lane;
        bool valid = i < NP;
        float2 v = valid ? __ldg(vals2 + i) : make_float2(0.f, 0.f);
        unsigned k0 = fkey(v.x), k1 = fkey(v.y);
        if (valid) ((uint2*)keys)[i] = make_uint2(k0, k1);
        hist_add(hist, k0 >> 24, valid, lane);
        hist_add(hist, k1 >> 24, valid, lane);
    }
    __syncwarp();
    unsigned prefix = ((unsigned)pivot256(hist, r, lane)) << 24;

    // refine passes over SMEM keys: bits 23..16, 15..8, 7..0
#pragma unroll
    for (int pass = 0; pass < 3; pass++) {
        const int shift = 16 - 8 * pass;
#pragma unroll
        for (int m = 0; m < 8; m++) hist[lane * 8 + m] = 0;
        __syncwarp();
        for (int base = 0; base < SOUT; base += 32) {
            int i = base + lane;
            bool valid = i < SOUT;
            unsigned ky = valid ? keys[i] : 0u;
            bool ok = valid && (((ky ^ prefix) >> (shift + 8)) == 0);
            hist_add(hist, (ky >> shift) & 255, ok, lane);
        }
        __syncwarp();
        prefix |= ((unsigned)pivot256(hist, r, lane)) << shift;
    }

    // stable compaction over SMEM keys (pairs): key>thr, plus first r ==thr
    const unsigned thr = prefix;
    int kept = 0, eqbudget = (int)r;
    for (int base = 0; base < NP; base += 32) {
        int ip = base + lane;
        bool valid = ip < NP;
        uint2 kk = valid ? ((const uint2*)keys)[ip] : make_uint2(0u, 0u);
        bool gt0 = valid && (kk.x > thr), eq0 = valid && (kk.x == thr);
        bool gt1 = valid && (kk.y > thr), eq1 = valid && (kk.y == thr);
        unsigned e0m = __ballot_sync(FULLMASK, eq0);
        unsigned e1m = __ballot_sync(FULLMASK, eq1);
        int eqb0 = __popc(e0m & lmlt) + __popc(e1m & lmlt);
        int eqb1 = eqb0 + (eq0 ? 1 : 0);
        bool kp0 = gt0 || (eq0 && eqb0 < eqbudget);
        bool kp1 = gt1 || (eq1 && eqb1 < eqbudget);
        unsigned b0 = __ballot_sync(FULLMASK, kp0);
        unsigned b1 = __ballot_sync(FULLMASK, kp1);
        int p0 = kept + __popc(b0 & lmlt) + __popc(b1 & lmlt);
        int p1 = p0 + (kp0 ? 1 : 0);
        if (kp0) dst[p0] = tanhf(unfkey(kk.x));
        if (kp1) dst[p1] = tanhf(unfkey(kk.y));
        kept += __popc(b0) + __popc(b1);
        int eqc = __popc(e0m) + __popc(e1m);
        eqbudget = eqbudget > eqc ? eqbudget - eqc : 0;
    }
}

__global__ void fc_kernel(const float* __restrict__ x, const float* __restrict__ fcw,
                          const float* __restrict__ fcb, float* __restrict__ out) {
    int b = blockIdx.x, m = threadIdx.x >> 5, lane = threadIdx.x & 31;
    const float* xr = x + b * 352;
    const float* wr = fcw + m * 352;
    float s = 0.f;
    for (int i = lane; i < 352; i += 32) s += xr[i] * wr[i];
#pragma unroll
    for (int d = 16; d > 0; d >>= 1) s += __shfl_down_sync(FULLMASK, s, d);
    if (lane == 0) out[b * 6 + m] = s + fcb[m];
}

extern "C" void kernel_launch(void* const* d_in, const int* in_sizes, int n_in,
                              void* d_out, int out_size) {
    const int*   tokens = (const int*)d_in[0];
    const float* emb = (const float*)d_in[1];
    const float* w1 = (const float*)d_in[2];
    const float* b1 = (const float*)d_in[3];
    const float* w2 = (const float*)d_in[4];
    const float* b2 = (const float*)d_in[5];
    const float* w3 = (const float*)d_in[6];
    const float* b3 = (const float*)d_in[7];
    const float* w4 = (const float*)d_in[8];
    const float* b4 = (const float*)d_in[9];
    const float* fcw = (const float*)d_in[10];
    const float* fcb = (const float*)d_in[11];
    float* out = (float*)d_out;

    float *y1, *y2, *y3, *y4, *p1, *p2, *p3, *p4;
    cudaGetSymbolAddress((void**)&y1, g_y1);
    cudaGetSymbolAddress((void**)&y2, g_y2);
    cudaGetSymbolAddress((void**)&y3, g_y3);
    cudaGetSymbolAddress((void**)&y4, g_y4);
    cudaGetSymbolAddress((void**)&p1, g_p1);
    cudaGetSymbolAddress((void**)&p2, g_p2);
    cudaGetSymbolAddress((void**)&p3, g_p3);
    cudaGetSymbolAddress((void**)&p4, g_p4);

    auto c1 = conv_kernel<2, 10, 7, 1024, true>;
    auto c2 = conv_kernel<20, 14, 5, 768, false>;
    auto c3 = conv_kernel<28, 18, 5, 512, false>;
    auto c4 = conv_kernel<36, 22, 3, 256, false>;
    size_t s1 = conv_smem_words(2, 10, 7) * 4;
    size_t s2 = conv_smem_words(20, 14, 5) * 4;
    size_t s3 = conv_smem_words(28, 18, 5) * 4;
    size_t s4 = conv_smem_words(36, 22, 3) * 4;
    cudaFuncSetAttribute(c1, cudaFuncAttributeMaxDynamicSharedMemorySize, (int)s1);
    cudaFuncSetAttribute(c2, cudaFuncAttributeMaxDynamicSharedMemorySize, (int)s2);
    cudaFuncSetAttribute(c3, cudaFuncAttributeMaxDynamicSharedMemorySize, (int)s3);
    cudaFuncSetAttribute(c4, cudaFuncAttributeMaxDynamicSharedMemorySize, (int)s4);

    auto m1 = kmax_kernel<1030, 768>;
    auto m2 = kmax_kernel<772, 512>;
    auto m3 = kmax_kernel<516, 256>;
    auto m4 = kmax_kernel<258, 4>;
    size_t km1 = 4 * (1030 + 256) * 4;
    size_t km2 = 4 * (772 + 256) * 4;
    size_t km3 = 4 * (516 + 256) * 4;
    size_t km4 = 4 * (258 + 256) * 4;
    cudaFuncSetAttribute(m1, cudaFuncAttributeMaxDynamicSharedMemorySize, (int)km1);
    cudaFuncSetAttribute(m2, cudaFuncAttributeMaxDynamicSharedMemorySize, (int)km2);
    cudaFuncSetAttribute(m3, cudaFuncAttributeMaxDynamicSharedMemorySize, (int)km3);
    cudaFuncSetAttribute(m4, cudaFuncAttributeMaxDynamicSharedMemorySize, (int)km4);

    // NTILE = ceil(SOUT / 128): L1 1030->9, L2 772->7, L3 516->5, L4 258->3
    c1<<<dim3(32 * 9, 64), CTH, s1>>>(nullptr, tokens, emb, w1, b1, p1);
    m1<<<64 * 320 / 4, 128, km1>>>(p1, y1);
    c2<<<dim3(16 * 7, 64), CTH, s2>>>(y1, nullptr, nullptr, w2, b2, p2);
    m2<<<64 * 224 / 4, 128, km2>>>(p2, y2);
    c3<<<dim3(8 * 5, 64), CTH, s3>>>(y2, nullptr, nullptr, w3, b3, p3);
    m3<<<64 * 144 / 4, 128, km3>>>(p3, y3);
    c4<<<dim3(4 * 3, 64), CTH, s4>>>(y3, nullptr, nullptr, w4, b4, p4);
    m4<<<64 * 88 / 4, 128, km4>>>(p4, y4);
    fc_kernel<<<64, 192>>>(y4, fcw, fcb, out);
}

// round 15
// speedup vs baseline: 1.1785x; 1.1785x over previous
#include <cuda_runtime.h>
#include <math.h>
#include <stdint.h>

#define FULLMASK 0xffffffffu

// pooled outputs (inputs to next layer)
__device__ __align__(16) float g_y1[64 * 320 * 768];
__device__ __align__(16) float g_y2[64 * 224 * 512];
__device__ __align__(16) float g_y3[64 * 144 * 256];
__device__ __align__(16) float g_y4[64 * 88 * 4];
// pre-pool conv outputs
__device__ __align__(16) float g_p1[64 * 320 * 1030];
__device__ __align__(16) float g_p2[64 * 224 * 772];
__device__ __align__(16) float g_p3[64 * 144 * 516];
__device__ __align__(16) float g_p4[64 * 88 * 258];

__device__ __forceinline__ unsigned long long fma2(unsigned long long a,
                                                   unsigned long long b,
                                                   unsigned long long c) {
    unsigned long long d;
    asm("fma.rn.f32x2 %0,%1,%2,%3;" : "=l"(d) : "l"(a), "l"(b), "l"(c));
    return d;
}
__device__ __forceinline__ void up2(unsigned long long v, float& x, float& y) {
    asm("mov.b64 {%0,%1},%2;" : "=f"(x), "=f"(y) : "l"(v));
}
__device__ __forceinline__ unsigned fkey(float f) {
    unsigned u = __float_as_uint(f);
    return (u & 0x80000000u) ? ~u : (u | 0x80000000u);
}
__device__ __forceinline__ float unfkey(unsigned k) {
    unsigned u = (k & 0x80000000u) ? (k ^ 0x80000000u) : ~k;
    return __uint_as_float(u);
}

#define TT 8   // outputs per thread

// grouped conv (+fold) -> pre-pool gmem. grid = (NG*NTILE, B).
// Each thread computes TWO f32x2 output-channel pairs (4 channels) x TT positions,
// reusing the input window wd[] for both pairs (halves input LDS traffic).
// block = NSLOT * (TSL/8) threads, one item per thread.
template <int IC, int NF, int KS, int SIN, int TSL, bool GATHER>
__global__ void __launch_bounds__(((NF / 2 + 1) / 2) * (TSL / 8))
conv_kernel(const float* __restrict__ xin, const int* __restrict__ tokens,
            const float* __restrict__ emb, const float* __restrict__ w,
            const float* __restrict__ bias, float* __restrict__ pre) {
    constexpr int PAD = KS - 1, SOUT = SIN + KS - 1;
    constexpr int SMT = TSL + 2 * KS;
    constexpr int NPAIR = NF / 2;
    constexpr int NSLOT = (NPAIR + 1) / 2;
    constexpr int NTILE = (SOUT + TSL - 1) / TSL;
    constexpr int IPG = IC / 2;
    constexpr int CTHL = NSLOT * (TSL / TT);

    extern __shared__ float sm[];
    float* sm_in = sm;                          // IC*SMT dup pairs (v,v)
    float* sm_w  = sm_in + 2 * IC * SMT;        // NPAIR*IC*KS f32x2
    float* sm_b2 = sm_w + 2 * NPAIR * IC * KS;  // NPAIR f32x2 (+overread pad)

    const int j = blockIdx.x / NTILE;
    const int st = blockIdx.x % NTILE;
    const int b = blockIdx.y, tid = threadIdx.x;
    const int NG = gridDim.x / NTILE;
    const int CHT = NG * NF;
    const int obase = st * TSL;

    if constexpr (GATHER) {
        for (int p = tid; p < SMT; p += CTHL) {
            int i = obase + p - PAD;
            float2 e = make_float2(0.f, 0.f);
            if (i >= 0 && i < SIN) {
                int tok = tokens[b * SIN + i];
                e = ((const float2*)emb)[tok * 32 + j];
            }
            ((float2*)sm_in)[p]       = make_float2(e.x, e.x);
            ((float2*)sm_in)[SMT + p] = make_float2(e.y, e.y);
        }
    } else {
        const float* src = xin + ((size_t)b * (NG * IC) + (size_t)j * IC) * SIN;
        for (int idx = tid; idx < IC * SMT; idx += CTHL) {
            int ic = idx / SMT, p = idx % SMT;
            int i = obase + p - PAD;
            float v = (i >= 0 && i < SIN) ? src[(size_t)ic * SIN + i] : 0.f;
            ((float2*)sm_in)[idx] = make_float2(v, v);
        }
    }
    for (int i = tid; i < NPAIR * IC * KS; i += CTHL) {
        int fp = i % NPAIR, rest = i / NPAIR;
        int k = rest % KS, ic = rest / KS;
        int g = 2 * j + (ic >= IPG ? 1 : 0);
        int ich = ic % IPG;
        const float* wb = w + (size_t)(g * NF) * IPG * KS + ich * KS + k;
        sm_w[2 * i]     = wb[(size_t)(2 * fp) * (IPG * KS)];
        sm_w[2 * i + 1] = wb[(size_t)(2 * fp + 1) * (IPG * KS)];
    }
    for (int i = tid; i < NPAIR; i += CTHL) {
        sm_b2[2 * i]     = bias[2 * j * NF + 2 * i]     + bias[(2 * j + 1) * NF + 2 * i];
        sm_b2[2 * i + 1] = bias[2 * j * NF + 2 * i + 1] + bias[(2 * j + 1) * NF + 2 * i + 1];
    }
    __syncthreads();

    // one item per thread: slot = tid % NSLOT (2 pairs), ot = tid / NSLOT
    {
        const int slot = tid % NSLOT, ot = tid / NSLOT, o0 = ot * TT;
        const int fp0 = 2 * slot;
        const bool has2 = (fp0 + 1) < NPAIR;
        unsigned long long acc0[TT], acc1[TT];
        {
            unsigned long long bb0 = *(const unsigned long long*)(sm_b2 + 2 * fp0);
            unsigned long long bb1 =
                *(const unsigned long long*)(sm_b2 + 2 * (has2 ? fp0 + 1 : fp0));
#pragma unroll
            for (int tt = 0; tt < TT; tt++) { acc0[tt] = bb0; acc1[tt] = bb1; }
        }
        const unsigned long long* xrow = (const unsigned long long*)sm_in + o0;
        const unsigned long long* wrow = (const unsigned long long*)sm_w + fp0;
        for (int ic = 0; ic < IC; ic++) {
            unsigned long long wd[TT + KS - 1];
#pragma unroll
            for (int q = 0; q < TT + KS - 1; q++) wd[q] = xrow[ic * SMT + q];
#pragma unroll
            for (int k = 0; k < KS; k++) {
                const unsigned long long* wp = wrow + (ic * KS + k) * NPAIR;
                unsigned long long wk0 = wp[0];
                unsigned long long wk1 = wp[1];  // overreads into sm_b2 when !has2: safe
#pragma unroll
                for (int tt = 0; tt < TT; tt++) {
                    acc0[tt] = fma2(wd[k + tt], wk0, acc0[tt]);
                    acc1[tt] = fma2(wd[k + tt], wk1, acc1[tt]);
                }
            }
        }
        const int c0 = j * NF + 2 * fp0;
        float* d0 = pre + ((size_t)b * CHT + c0) * SOUT;
        float* d1 = d0 + SOUT;
        float* d2 = d1 + SOUT;
        float* d3 = d2 + SOUT;
#pragma unroll
        for (int tt = 0; tt < TT; tt++) {
            int o = obase + o0 + tt;
            if (o < SOUT) {
                float x_, y_;
                up2(acc0[tt], x_, y_);
                d0[o] = x_;
                d1[o] = y_;
                if (has2) {
                    up2(acc1[tt], x_, y_);
                    d2[o] = x_;
                    d3[o] = y_;
                }
            }
        }
    }
}

// pivot over 256-bin per-warp hist (8 bins/lane). updates r (r -= count above bin).
__device__ __forceinline__ int pivot256(const unsigned* hist, unsigned& r, int lane) {
    unsigned h[8], s = 0;
#pragma unroll
    for (int m = 0; m < 8; m++) { h[m] = hist[lane * 8 + m]; s += h[m]; }
    unsigned run = s;  // suffix sum over lanes (bins ascend with lane)
#pragma unroll
    for (int d = 1; d < 32; d <<= 1) {
        unsigned v = __shfl_down_sync(FULLMASK, run, d);
        if (lane + d < 32) run += v;
    }
    unsigned above = run - s;
    bool mine = (above < r) && (run >= r);
    unsigned a2 = above, gtc = 0;
    int bsel = 0;
    bool found = false;
#pragma unroll
    for (int m = 7; m >= 0; m--) {
        unsigned na = a2 + h[m];
        if (!found && na >= r) { found = true; bsel = lane * 8 + m; gtc = a2; }
        a2 = na;
    }
    unsigned msk = __ballot_sync(FULLMASK, mine);
    int src = __ffs(msk) - 1;
    bsel = __shfl_sync(FULLMASK, bsel, src);
    gtc  = __shfl_sync(FULLMASK, gtc, src);
    r -= gtc;
    return bsel;
}

// warp-per-row top-KOUT (order preserving, lax.top_k ties) + tanh. (R12 version)
template <int SOUT, int KOUT>
__global__ void __launch_bounds__(128)
kmax_kernel(const float* __restrict__ pre, float* __restrict__ yout) {
    constexpr int NP = SOUT / 2;  // SOUT even
    extern __shared__ unsigned ksm[];
    const int warp = threadIdx.x >> 5, lane = threadIdx.x & 31;
    const unsigned lmlt = (1u << lane) - 1u;
    unsigned* keys = ksm + warp * (SOUT + 256);
    unsigned* hist = keys + SOUT;

    const int row = blockIdx.x * 4 + warp;
    const float2* vals2 = (const float2*)(pre + (size_t)row * SOUT);
    float* dst = yout + (size_t)row * KOUT;

    unsigned r = KOUT;
#pragma unroll
    for (int m = 0; m < 8; m++) hist[lane * 8 + m] = 0;
    __syncwarp();
    for (int i = lane; i < NP; i += 32) {
        float2 v = __ldg(vals2 + i);
        unsigned k0 = fkey(v.x), k1 = fkey(v.y);
        ((uint2*)keys)[i] = make_uint2(k0, k1);
        atomicAdd(&hist[k0 >> 24], 1u);
        atomicAdd(&hist[k1 >> 24], 1u);
    }
    __syncwarp();
    unsigned prefix = ((unsigned)pivot256(hist, r, lane)) << 24;

#pragma unroll
    for (int pass = 0; pass < 3; pass++) {
        const int shift = 16 - 8 * pass;
#pragma unroll
        for (int m = 0; m < 8; m++) hist[lane * 8 + m] = 0;
        __syncwarp();
        for (int i = lane; i < SOUT; i += 32) {
            unsigned ky = keys[i];
            if (((ky ^ prefix) >> (shift + 8)) == 0)
                atomicAdd(&hist[(ky >> shift) & 255], 1u);
        }
        __syncwarp();
        prefix |= ((unsigned)pivot256(hist, r, lane)) << shift;
    }

    const unsigned thr = prefix;
    int kept = 0, eqbudget = (int)r;
    for (int base = 0; base < NP; base += 32) {
        int ip = base + lane;
        bool valid = ip < NP;
        uint2 kk = valid ? ((const uint2*)keys)[ip] : make_uint2(0u, 0u);
        bool gt0 = valid && (kk.x > thr), eq0 = valid && (kk.x == thr);
        bool gt1 = valid && (kk.y > thr), eq1 = valid && (kk.y == thr);
        unsigned e0m = __ballot_sync(FULLMASK, eq0);
        unsigned e1m = __ballot_sync(FULLMASK, eq1);
        int eqb0 = __popc(e0m & lmlt) + __popc(e1m & lmlt);
        int eqb1 = eqb0 + (eq0 ? 1 : 0);
        bool kp0 = gt0 || (eq0 && eqb0 < eqbudget);
        bool kp1 = gt1 || (eq1 && eqb1 < eqbudget);
        unsigned b0 = __ballot_sync(FULLMASK, kp0);
        unsigned b1 = __ballot_sync(FULLMASK, kp1);
        int p0 = kept + __popc(b0 & lmlt) + __popc(b1 & lmlt);
        int p1 = p0 + (kp0 ? 1 : 0);
        if (kp0) dst[p0] = tanhf(unfkey(kk.x));
        if (kp1) dst[p1] = tanhf(unfkey(kk.y));
        kept += __popc(b0) + __popc(b1);
        int eqc = __popc(e0m) + __popc(e1m);
        eqbudget = eqbudget > eqc ? eqbudget - eqc : 0;
    }
}

__global__ void fc_kernel(const float* __restrict__ x, const float* __restrict__ fcw,
                          const float* __restrict__ fcb, float* __restrict__ out) {
    int b = blockIdx.x, m = threadIdx.x >> 5, lane = threadIdx.x & 31;
    const float* xr = x + b * 352;
    const float* wr = fcw + m * 352;
    float s = 0.f;
    for (int i = lane; i < 352; i += 32) s += xr[i] * wr[i];
#pragma unroll
    for (int d = 16; d > 0; d >>= 1) s += __shfl_down_sync(FULLMASK, s, d);
    if (lane == 0) out[b * 6 + m] = s + fcb[m];
}

__host__ constexpr int conv_smem_b(int IC, int NPAIR, int KS, int TSL) {
    int SMT = TSL + 2 * KS;
    return (2 * IC * SMT + 2 * NPAIR * IC * KS + 2 * NPAIR + 4) * 4;
}

extern "C" void kernel_launch(void* const* d_in, const int* in_sizes, int n_in,
                              void* d_out, int out_size) {
    const int*   tokens = (const int*)d_in[0];
    const float* emb = (const float*)d_in[1];
    const float* w1 = (const float*)d_in[2];
    const float* b1 = (const float*)d_in[3];
    const float* w2 = (const float*)d_in[4];
    const float* b2 = (const float*)d_in[5];
    const float* w3 = (const float*)d_in[6];
    const float* b3 = (const float*)d_in[7];
    const float* w4 = (const float*)d_in[8];
    const float* b4 = (const float*)d_in[9];
    const float* fcw = (const float*)d_in[10];
    const float* fcb = (const float*)d_in[11];
    float* out = (float*)d_out;

    float *y1, *y2, *y3, *y4, *p1, *p2, *p3, *p4;
    cudaGetSymbolAddress((void**)&y1, g_y1);
    cudaGetSymbolAddress((void**)&y2, g_y2);
    cudaGetSymbolAddress((void**)&y3, g_y3);
    cudaGetSymbolAddress((void**)&y4, g_y4);
    cudaGetSymbolAddress((void**)&p1, g_p1);
    cudaGetSymbolAddress((void**)&p2, g_p2);
    cudaGetSymbolAddress((void**)&p3, g_p3);
    cudaGetSymbolAddress((void**)&p4, g_p4);

    // TSL: L1 208 (NTILE 5), L2 200 (4), L3 176 (3), L4 136 (2)
    auto c1 = conv_kernel<2, 10, 7, 1024, 208, true>;
    auto c2 = conv_kernel<20, 14, 5, 768, 200, false>;
    auto c3 = conv_kernel<28, 18, 5, 512, 176, false>;
    auto c4 = conv_kernel<36, 22, 3, 256, 136, false>;
    size_t s1 = conv_smem_b(2, 5, 7, 208);
    size_t s2 = conv_smem_b(20, 7, 5, 200);
    size_t s3 = conv_smem_b(28, 9, 5, 176);
    size_t s4 = conv_smem_b(36, 11, 3, 136);
    cudaFuncSetAttribute(c1, cudaFuncAttributeMaxDynamicSharedMemorySize, (int)s1);
    cudaFuncSetAttribute(c2, cudaFuncAttributeMaxDynamicSharedMemorySize, (int)s2);
    cudaFuncSetAttribute(c3, cudaFuncAttributeMaxDynamicSharedMemorySize, (int)s3);
    cudaFuncSetAttribute(c4, cudaFuncAttributeMaxDynamicSharedMemorySize, (int)s4);

    auto m1 = kmax_kernel<1030, 768>;
    auto m2 = kmax_kernel<772, 512>;
    auto m3 = kmax_kernel<516, 256>;
    auto m4 = kmax_kernel<258, 4>;
    size_t km1 = 4 * (1030 + 256) * 4;
    size_t km2 = 4 * (772 + 256) * 4;
    size_t km3 = 4 * (516 + 256) * 4;
    size_t km4 = 4 * (258 + 256) * 4;
    cudaFuncSetAttribute(m1, cudaFuncAttributeMaxDynamicSharedMemorySize, (int)km1);
    cudaFuncSetAttribute(m2, cudaFuncAttributeMaxDynamicSharedMemorySize, (int)km2);
    cudaFuncSetAttribute(m3, cudaFuncAttributeMaxDynamicSharedMemorySize, (int)km3);
    cudaFuncSetAttribute(m4, cudaFuncAttributeMaxDynamicSharedMemorySize, (int)km4);

    // blocks = NSLOT*(TSL/8): L1 3*26=78, L2 4*25=100, L3 5*22=110, L4 6*17=102
    c1<<<dim3(32 * 5, 64), 78, s1>>>(nullptr, tokens, emb, w1, b1, p1);
    m1<<<64 * 320 / 4, 128, km1>>>(p1, y1);
    c2<<<dim3(16 * 4, 64), 100, s2>>>(y1, nullptr, nullptr, w2, b2, p2);
    m2<<<64 * 224 / 4, 128, km2>>>(p2, y2);
    c3<<<dim3(8 * 3, 64), 110, s3>>>(y2, nullptr, nullptr, w3, b3, p3);
    m3<<<64 * 144 / 4, 128, km3>>>(p3, y3);
    c4<<<dim3(4 * 2, 64), 102, s4>>>(y3, nullptr, nullptr, w4, b4, p4);
    m4<<<64 * 88 / 4, 128, km4>>>(p4, y4);
    fc_kernel<<<64, 192>>>(y4, fcw, fcb, out);
}

// round 16
// speedup vs baseline: 1.2947x; 1.0986x over previous
#include <cuda_runtime.h>
#include <math.h>
#include <stdint.h>

#define FULLMASK 0xffffffffu

// pooled outputs (inputs to next layer)
__device__ __align__(16) float g_y1[64 * 320 * 768];
__device__ __align__(16) float g_y2[64 * 224 * 512];
__device__ __align__(16) float g_y3[64 * 144 * 256];
__device__ __align__(16) float g_y4[64 * 88 * 4];
// pre-pool conv outputs
__device__ __align__(16) float g_p1[64 * 320 * 1030];
__device__ __align__(16) float g_p2[64 * 224 * 772];
__device__ __align__(16) float g_p3[64 * 144 * 516];
__device__ __align__(16) float g_p4[64 * 88 * 258];

__device__ __forceinline__ unsigned long long fma2(unsigned long long a,
                                                   unsigned long long b,
                                                   unsigned long long c) {
    unsigned long long d;
    asm("fma.rn.f32x2 %0,%1,%2,%3;" : "=l"(d) : "l"(a), "l"(b), "l"(c));
    return d;
}
__device__ __forceinline__ unsigned fkey(float f) {
    unsigned u = __float_as_uint(f);
    return (u & 0x80000000u) ? ~u : (u | 0x80000000u);
}
__device__ __forceinline__ float unfkey(unsigned k) {
    unsigned u = (k & 0x80000000u) ? (k ^ 0x80000000u) : ~k;
    return __uint_as_float(u);
}

#define CTH 128   // conv block
#define TS  128   // seq outputs per conv CTA
#define TT  8     // outputs per thread

__host__ __device__ constexpr int conv_smem_words(int IC, int NF, int KS) {
    const int SMT = TS + 2 * KS;
    // input(dup) + weights + bias + sm_out (NPAIR*TS float2)
    return 2 * IC * SMT + 2 * (NF / 2) * IC * KS + 2 * (NF / 2) + (NF / 2) * TS * 2;
}

// no-op pad kernel: shifts ncu's -s window so a conv gets profiled
__global__ void pad_kernel() {}

// grouped conv (+fold) -> pre-pool gmem. grid.x = NG*NTILE, grid.y = B.
template <int IC, int NF, int KS, int SIN, bool GATHER>
__global__ void __launch_bounds__(CTH)
conv_kernel(const float* __restrict__ xin, const int* __restrict__ tokens,
            const float* __restrict__ emb, const float* __restrict__ w,
            const float* __restrict__ bias, float* __restrict__ pre) {
    constexpr int PAD = KS - 1, SOUT = SIN + KS - 1;
    constexpr int SMT = TS + 2 * KS;
    constexpr int NPAIR = NF / 2;
    constexpr int NTILE = (SOUT + TS - 1) / TS;
    constexpr int IPG = IC / 2;

    extern __shared__ float sm[];
    float* sm_in = sm;                          // IC*SMT dup pairs (v,v)
    float* sm_w  = sm_in + 2 * IC * SMT;        // NPAIR*IC*KS f32x2
    float* sm_b2 = sm_w + 2 * NPAIR * IC * KS;  // NPAIR f32x2
    float2* sm_out = (float2*)(sm_b2 + 2 * NPAIR);  // [NPAIR][TS] f32x2

    const int j = blockIdx.x / NTILE;
    const int st = blockIdx.x % NTILE;
    const int b = blockIdx.y, tid = threadIdx.x;
    const int NG = gridDim.x / NTILE;
    const int CHT = NG * NF;
    const int obase = st * TS;

    if constexpr (GATHER) {
        for (int p = tid; p < SMT; p += CTH) {
            int i = obase + p - PAD;
            float2 e = make_float2(0.f, 0.f);
            if (i >= 0 && i < SIN) {
                int tok = tokens[b * SIN + i];
                e = ((const float2*)emb)[tok * 32 + j];
            }
            ((float2*)sm_in)[p]       = make_float2(e.x, e.x);
            ((float2*)sm_in)[SMT + p] = make_float2(e.y, e.y);
        }
    } else {
        const float* src = xin + ((size_t)b * (NG * IC) + (size_t)j * IC) * SIN;
        for (int idx = tid; idx < IC * SMT; idx += CTH) {
            int ic = idx / SMT, p = idx % SMT;
            int i = obase + p - PAD;
            float v = (i >= 0 && i < SIN) ? src[(size_t)ic * SIN + i] : 0.f;
            ((float2*)sm_in)[idx] = make_float2(v, v);
        }
    }
    for (int i = tid; i < NPAIR * IC * KS; i += CTH) {
        int fp = i % NPAIR, rest = i / NPAIR;
        int k = rest % KS, ic = rest / KS;
        int g = 2 * j + (ic >= IPG ? 1 : 0);
        int ich = ic % IPG;
        const float* wb = w + (size_t)(g * NF) * IPG * KS + ich * KS + k;
        sm_w[2 * i]     = wb[(size_t)(2 * fp) * (IPG * KS)];
        sm_w[2 * i + 1] = wb[(size_t)(2 * fp + 1) * (IPG * KS)];
    }
    for (int i = tid; i < NPAIR; i += CTH) {
        sm_b2[2 * i]     = bias[2 * j * NF + 2 * i]     + bias[(2 * j + 1) * NF + 2 * i];
        sm_b2[2 * i + 1] = bias[2 * j * NF + 2 * i + 1] + bias[(2 * j + 1) * NF + 2 * i + 1];
    }
    __syncthreads();

    constexpr int ITEMS = NPAIR * (TS / TT);
    for (int t = tid; t < ITEMS; t += CTH) {
        const int fp = t % NPAIR, ot = t / NPAIR, o0 = ot * TT;
        unsigned long long acc[TT];
        unsigned long long b2 = *(const unsigned long long*)(sm_b2 + 2 * fp);
#pragma unroll
        for (int tt = 0; tt < TT; tt++) acc[tt] = b2;
        const unsigned long long* xrow = (const unsigned long long*)sm_in + o0;
        const unsigned long long* wrow = (const unsigned long long*)sm_w + fp;
        for (int ic = 0; ic < IC; ic++) {
            unsigned long long wd[TT + KS - 1];
#pragma unroll
            for (int q = 0; q < TT + KS - 1; q++) wd[q] = xrow[ic * SMT + q];
#pragma unroll
            for (int k = 0; k < KS; k++) {
                unsigned long long wk = wrow[(ic * KS + k) * NPAIR];
#pragma unroll
                for (int tt = 0; tt < TT; tt++) acc[tt] = fma2(wd[k + tt], wk, acc[tt]);
            }
        }
        // stage into SMEM (channel-pair-major) for coalesced global store
#pragma unroll
        for (int tt = 0; tt < TT; tt++)
            *(unsigned long long*)&sm_out[fp * TS + o0 + tt] = acc[tt];
    }
    __syncthreads();

    // cooperative coalesced store: lanes cover consecutive float2 of one channel row
    for (int it = tid; it < NF * (TS / 2); it += CTH) {
        int c = it / (TS / 2), o2 = it % (TS / 2);
        int o = obase + 2 * o2;
        if (o < SOUT) {  // SOUT even, o even -> o+1 also in range
            int fp = c >> 1;
            float2 a0 = sm_out[fp * TS + 2 * o2];
            float2 a1 = sm_out[fp * TS + 2 * o2 + 1];
            float v0 = (c & 1) ? a0.y : a0.x;
            float v1 = (c & 1) ? a1.y : a1.x;
            float* drow = pre + ((size_t)b * CHT + (size_t)(j * NF + c)) * SOUT;
            ((float2*)drow)[o / 2] = make_float2(v0, v1);
        }
    }
}

// pivot over 256-bin per-warp hist (8 bins/lane). updates r (r -= count above bin).
__device__ __forceinline__ int pivot256(const unsigned* hist, unsigned& r, int lane) {
    unsigned h[8], s = 0;
#pragma unroll
    for (int m = 0; m < 8; m++) { h[m] = hist[lane * 8 + m]; s += h[m]; }
    unsigned run = s;  // suffix sum over lanes (bins ascend with lane)
#pragma unroll
    for (int d = 1; d < 32; d <<= 1) {
        unsigned v = __shfl_down_sync(FULLMASK, run, d);
        if (lane + d < 32) run += v;
    }
    unsigned above = run - s;
    bool mine = (above < r) && (run >= r);
    unsigned a2 = above, gtc = 0;
    int bsel = 0;
    bool found = false;
#pragma unroll
    for (int m = 7; m >= 0; m--) {
        unsigned na = a2 + h[m];
        if (!found && na >= r) { found = true; bsel = lane * 8 + m; gtc = a2; }
        a2 = na;
    }
    unsigned msk = __ballot_sync(FULLMASK, mine);
    int src = __ffs(msk) - 1;
    bsel = __shfl_sync(FULLMASK, bsel, src);
    gtc  = __shfl_sync(FULLMASK, gtc, src);
    r -= gtc;
    return bsel;
}

// warp-per-row top-KOUT (order preserving, lax.top_k ties) + tanh. (R12 version)
template <int SOUT, int KOUT>
__global__ void __launch_bounds__(128)
kmax_kernel(const float* __restrict__ pre, float* __restrict__ yout) {
    constexpr int NP = SOUT / 2;  // SOUT even
    extern __shared__ unsigned ksm[];
    const int warp = threadIdx.x >> 5, lane = threadIdx.x & 31;
    const unsigned lmlt = (1u << lane) - 1u;
    unsigned* keys = ksm + warp * (SOUT + 256);
    unsigned* hist = keys + SOUT;

    const int row = blockIdx.x * 4 + warp;
    const float2* vals2 = (const float2*)(pre + (size_t)row * SOUT);
    float* dst = yout + (size_t)row * KOUT;

    unsigned r = KOUT;
#pragma unroll
    for (int m = 0; m < 8; m++) hist[lane * 8 + m] = 0;
    __syncwarp();
    for (int i = lane; i < NP; i += 32) {
        float2 v = __ldg(vals2 + i);
        unsigned k0 = fkey(v.x), k1 = fkey(v.y);
        ((uint2*)keys)[i] = make_uint2(k0, k1);
        atomicAdd(&hist[k0 >> 24], 1u);
        atomicAdd(&hist[k1 >> 24], 1u);
    }
    __syncwarp();
    unsigned prefix = ((unsigned)pivot256(hist, r, lane)) << 24;

#pragma unroll
    for (int pass = 0; pass < 3; pass++) {
        const int shift = 16 - 8 * pass;
#pragma unroll
        for (int m = 0; m < 8; m++) hist[lane * 8 + m] = 0;
        __syncwarp();
        for (int i = lane; i < SOUT; i += 32) {
            unsigned ky = keys[i];
            if (((ky ^ prefix) >> (shift + 8)) == 0)
                atomicAdd(&hist[(ky >> shift) & 255], 1u);
        }
        __syncwarp();
        prefix |= ((unsigned)pivot256(hist, r, lane)) << shift;
    }

    const unsigned thr = prefix;
    int kept = 0, eqbudget = (int)r;
    for (int base = 0; base < NP; base += 32) {
        int ip = base + lane;
        bool valid = ip < NP;
        uint2 kk = valid ? ((const uint2*)keys)[ip] : make_uint2(0u, 0u);
        bool gt0 = valid && (kk.x > thr), eq0 = valid && (kk.x == thr);
        bool gt1 = valid && (kk.y > thr), eq1 = valid && (kk.y == thr);
        unsigned e0m = __ballot_sync(FULLMASK, eq0);
        unsigned e1m = __ballot_sync(FULLMASK, eq1);
        int eqb0 = __popc(e0m & lmlt) + __popc(e1m & lmlt);
        int eqb1 = eqb0 + (eq0 ? 1 : 0);
        bool kp0 = gt0 || (eq0 && eqb0 < eqbudget);
        bool kp1 = gt1 || (eq1 && eqb1 < eqbudget);
        unsigned b0 = __ballot_sync(FULLMASK, kp0);
        unsigned b1 = __ballot_sync(FULLMASK, kp1);
        int p0 = kept + __popc(b0 & lmlt) + __popc(b1 & lmlt);
        int p1 = p0 + (kp0 ? 1 : 0);
        if (kp0) dst[p0] = tanhf(unfkey(kk.x));
        if (kp1) dst[p1] = tanhf(unfkey(kk.y));
        kept += __popc(b0) + __popc(b1);
        int eqc = __popc(e0m) + __popc(e1m);
        eqbudget = eqbudget > eqc ? eqbudget - eqc : 0;
    }
}

__global__ void fc_kernel(const float* __restrict__ x, const float* __restrict__ fcw,
                          const float* __restrict__ fcb, float* __restrict__ out) {
    int b = blockIdx.x, m = threadIdx.x >> 5, lane = threadIdx.x & 31;
    const float* xr = x + b * 352;
    const float* wr = fcw + m * 352;
    float s = 0.f;
    for (int i = lane; i < 352; i += 32) s += xr[i] * wr[i];
#pragma unroll
    for (int d = 16; d > 0; d >>= 1) s += __shfl_down_sync(FULLMASK, s, d);
    if (lane == 0) out[b * 6 + m] = s + fcb[m];
}

extern "C" void kernel_launch(void* const* d_in, const int* in_sizes, int n_in,
                              void* d_out, int out_size) {
    const int*   tokens = (const int*)d_in[0];
    const float* emb = (const float*)d_in[1];
    const float* w1 = (const float*)d_in[2];
    const float* b1 = (const float*)d_in[3];
    const float* w2 = (const float*)d_in[4];
    const float* b2 = (const float*)d_in[5];
    const float* w3 = (const float*)d_in[6];
    const float* b3 = (const float*)d_in[7];
    const float* w4 = (const float*)d_in[8];
    const float* b4 = (const float*)d_in[9];
    const float* fcw = (const float*)d_in[10];
    const float* fcb = (const float*)d_in[11];
    float* out = (float*)d_out;

    float *y1, *y2, *y3, *y4, *p1, *p2, *p3, *p4;
    cudaGetSymbolAddress((void**)&y1, g_y1);
    cudaGetSymbolAddress((void**)&y2, g_y2);
    cudaGetSymbolAddress((void**)&y3, g_y3);
    cudaGetSymbolAddress((void**)&y4, g_y4);
    cudaGetSymbolAddress((void**)&p1, g_p1);
    cudaGetSymbolAddress((void**)&p2, g_p2);
    cudaGetSymbolAddress((void**)&p3, g_p3);
    cudaGetSymbolAddress((void**)&p4, g_p4);

    auto c1 = conv_kernel<2, 10, 7, 1024, true>;
    auto c2 = conv_kernel<20, 14, 5, 768, false>;
    auto c3 = conv_kernel<28, 18, 5, 512, false>;
    auto c4 = conv_kernel<36, 22, 3, 256, false>;
    size_t s1 = conv_smem_words(2, 10, 7) * 4;
    size_t s2 = conv_smem_words(20, 14, 5) * 4;
    size_t s3 = conv_smem_words(28, 18, 5) * 4;
    size_t s4 = conv_smem_words(36, 22, 3) * 4;
    cudaFuncSetAttribute(c1, cudaFuncAttributeMaxDynamicSharedMemorySize, (int)s1);
    cudaFuncSetAttribute(c2, cudaFuncAttributeMaxDynamicSharedMemorySize, (int)s2);
    cudaFuncSetAttribute(c3, cudaFuncAttributeMaxDynamicSharedMemorySize, (int)s3);
    cudaFuncSetAttribute(c4, cudaFuncAttributeMaxDynamicSharedMemorySize, (int)s4);

    auto m1 = kmax_kernel<1030, 768>;
    auto m2 = kmax_kernel<772, 512>;
    auto m3 = kmax_kernel<516, 256>;
    auto m4 = kmax_kernel<258, 4>;
    size_t km1 = 4 * (1030 + 256) * 4;
    size_t km2 = 4 * (772 + 256) * 4;
    size_t km3 = 4 * (516 + 256) * 4;
    size_t km4 = 4 * (258 + 256) * 4;
    cudaFuncSetAttribute(m1, cudaFuncAttributeMaxDynamicSharedMemorySize, (int)km1);
    cudaFuncSetAttribute(m2, cudaFuncAttributeMaxDynamicSharedMemorySize, (int)km2);
    cudaFuncSetAttribute(m3, cudaFuncAttributeMaxDynamicSharedMemorySize, (int)km3);
    cudaFuncSetAttribute(m4, cudaFuncAttributeMaxDynamicSharedMemorySize, (int)km4);

    // launch 0: pad so ncu's -s 5 window lands on conv2 (diagnostic, ~1us)
    pad_kernel<<<1, 32>>>();
    // NTILE = ceil(SOUT / 128): L1 1030->9, L2 772->7, L3 516->5, L4 258->3
    c1<<<dim3(32 * 9, 64), CTH, s1>>>(nullptr, tokens, emb, w1, b1, p1);
    m1<<<64 * 320 / 4, 128, km1>>>(p1, y1);
    c2<<<dim3(16 * 7, 64), CTH, s2>>>(y1, nullptr, nullptr, w2, b2, p2);
    m2<<<64 * 224 / 4, 128, km2>>>(p2, y2);
    c3<<<dim3(8 * 5, 64), CTH, s3>>>(y2, nullptr, nullptr, w3, b3, p3);
    m3<<<64 * 144 / 4, 128, km3>>>(p3, y3);
    c4<<<dim3(4 * 3, 64), CTH, s4>>>(y3, nullptr, nullptr, w4, b4, p4);
    m4<<<64 * 88 / 4, 128, km4>>>(p4, y4);
    fc_kernel<<<64, 192>>>(y4, fcw, fcb, out);
}